// round 1
// baseline (speedup 1.0000x reference)
#include <cuda_runtime.h>
#include <math.h>

#define N_    256
#define B_    64
#define FIN   5
#define NE_   65536

// ---------------- scratch (no allocations allowed) ----------------
__device__ __align__(16) float g_mats[4 * NE_];   // [A, M0, M1, M2], row-major [i*N+j]
__device__ float g_dis[N_];
__device__ float g_logits[3];

// ---------------- packed f32x2 helpers ----------------
static __device__ __forceinline__ unsigned long long ffma2(unsigned long long a,
                                                           unsigned long long b,
                                                           unsigned long long c) {
    unsigned long long d;
    asm("fma.rn.f32x2 %0, %1, %2, %3;" : "=l"(d) : "l"(a), "l"(b), "l"(c));
    return d;
}
static __device__ __forceinline__ unsigned long long fadd2(unsigned long long a,
                                                           unsigned long long b) {
    unsigned long long d;
    asm("add.rn.f32x2 %0, %1, %2;" : "=l"(d) : "l"(a), "l"(b));
    return d;
}
static __device__ __forceinline__ unsigned long long dup2(float v) {
    unsigned long long d;
    unsigned int u = __float_as_uint(v);
    asm("mov.b64 %0, {%1, %1};" : "=l"(d) : "r"(u));
    return d;
}
static __device__ __forceinline__ float2 unpack2(unsigned long long v) {
    unsigned int lo, hi;
    asm("mov.b64 {%0, %1}, %2;" : "=r"(lo), "=r"(hi) : "l"(v));
    return make_float2(__uint_as_float(lo), __uint_as_float(hi));
}

// ---------------- digamma (double) ----------------
static __device__ double digamma_d(double x) {
    double r = 0.0;
    while (x < 8.0) { r -= 1.0 / x; x += 1.0; }
    double f = 1.0 / (x * x);
    double s = f * (1.0 / 12.0 - f * (1.0 / 120.0 - f * (1.0 / 252.0 - f * (1.0 / 240.0 - f * (1.0 / 132.0)))));
    return r + log(x) - 0.5 / x - s;
}

// ---------------- kernel 1: per-layer scalars, kld, drop_rates ----------------
__global__ void scalar_kernel(const float* __restrict__ a_uc,
                              const float* __restrict__ b_uc,
                              const float* __restrict__ u_pi,
                              float* __restrict__ out) {
    int l = threadIdx.x;
    __shared__ float kld_s[3];
    if (l < 3) {
        double au = (double)a_uc[l]; if (au < -10.0) au = -10.0;
        double bu = (double)b_uc[l]; if (bu < -10.0) bu = -10.0; if (bu > 50.0) bu = 50.0;
        double a = log1p(exp(au));
        double b = log1p(exp(bu));
        double up = (double)u_pi[l];
        if (up < 1e-6) up = 1e-6;
        if (up > 1.0 - 1e-6) up = 1.0 - 1e-6;
        double pi = pow(1.0 - pow(up, 1.0 / b), 1.0 / a);
        double logits = log(pi) - log1p(-pi);
        g_logits[l] = (float)logits;
        out[193 + l] = (float)pi;   // drop_rates
        const double euler = 0.577215664901532;
        double kld = (1.0 - 0.8 / a) * (-euler - digamma_d(b) - 1.0 / b)
                   + log(a * b + 1e-10) - log(0.8) - (b - 1.0) / b;
        kld_s[l] = (float)kld;
    }
    __syncthreads();
    if (l == 0) out[192] = kld_s[0] + kld_s[1] + kld_s[2];   // kld_loss
}

// ---------------- kernel 2: degree / dis ----------------
__global__ void deg_kernel(const float* __restrict__ ewp) {
    int i = blockIdx.x, j = threadIdx.x;
    int r = max(i, j), c = min(i, j);
    float w = ewp[(r * (r + 1)) / 2 + c];
    float v = fabsf(w);
    __shared__ float sh[8];
    #pragma unroll
    for (int o = 16; o > 0; o >>= 1) v += __shfl_xor_sync(0xffffffffu, v, o);
    if ((j & 31) == 0) sh[j >> 5] = v;
    __syncthreads();
    if (j == 0) {
        float s = 0.f;
        #pragma unroll
        for (int k = 0; k < 8; k++) s += sh[k];
        g_dis[i] = (s > 0.f) ? rsqrtf(s) : 0.f;
    }
}

// ---------------- kernel 3: build A and the three masked matrices ----------------
__global__ void mats_kernel(const float* __restrict__ ewp,
                            const float* __restrict__ u_rb) {
    int i = blockIdx.x, j = threadIdx.x;
    int r = max(i, j), c = min(i, j);
    float w = ewp[(r * (r + 1)) / 2 + c];
    float aij = g_dis[i] * w * g_dis[j];
    int e = i * N_ + j;
    g_mats[e] = aij;
    #pragma unroll
    for (int l = 0; l < 3; l++) {
        float ur = u_rb[l * NE_ + e];
        ur = fminf(fmaxf(ur, 1e-6f), 1.0f - 1e-6f);
        float t = (g_logits[l] + logf(ur) - logf(1.0f - ur)) * (1.0f / 0.6f);
        float z = 1.0f / (1.0f + expf(-t));
        g_mats[(l + 1) * NE_ + e] = z * aij;
    }
}

// ---------------- kernel 4: fused 5-conv chain + lin/relu/pool/fc head ----------
// One block per graph. X lives in shared; matrices stream from L2 (shared
// across all 64 blocks). Thread t: j-group j4 = t&63 (columns 4*j4..4*j4+3),
// K-range quarter q = t>>6 (rows q*64..q*64+63). Packed f32x2 FMAs, pairs are
// (j, j+1) column pairs straight out of the float4 load.
__global__ void __launch_bounds__(256) conv_head_kernel(
        const float* __restrict__ x,
        const float* __restrict__ lin_w, const float* __restrict__ lin_b,
        const float* __restrict__ fc_w,  const float* __restrict__ fc_b,
        float* __restrict__ out) {
    __shared__ unsigned long long Xd[N_ * FIN];        // duplicated (v,v)   10 KB
    __shared__ float Xp[N_ * FIN];                     // plain              5 KB
    __shared__ unsigned long long Ps[4 * 128 * FIN];   // K-split partials  20 KB
    __shared__ float PoolBuf[2 * 128];

    int b = blockIdx.x, t = threadIdx.x;
    int j4 = t & 63, q = t >> 6;

    // load this graph's X
    {
        const float* xb = x + b * N_ * FIN;
        #pragma unroll
        for (int f = 0; f < FIN; f++) {
            float v = xb[t * FIN + f];
            Xp[t * FIN + f] = v;
            Xd[t * FIN + f] = dup2(v);
        }
    }
    __syncthreads();

    #pragma unroll 1
    for (int cs = 0; cs < 5; cs++) {
        // matrix order: M0, A, M1, A, M2  ->  index 1,0,2,0,3
        int mi = (cs & 1) ? 0 : ((cs >> 1) + 1);
        const ulonglong2* M2v = (const ulonglong2*)(g_mats + mi * NE_);

        unsigned long long acc[2][FIN];
        #pragma unroll
        for (int jp = 0; jp < 2; jp++)
            #pragma unroll
            for (int f = 0; f < FIN; f++) acc[jp][f] = 0ull;

        int i0 = q * 64;
        #pragma unroll 4
        for (int ii = 0; ii < 64; ii++) {
            int i = i0 + ii;
            ulonglong2 mv = M2v[i * 64 + j4];            // M[i][4*j4 .. 4*j4+3]
            const unsigned long long* xr = &Xd[i * FIN];
            #pragma unroll
            for (int f = 0; f < FIN; f++) {
                unsigned long long xv = xr[f];
                acc[0][f] = ffma2(mv.x, xv, acc[0][f]);  // cols (4j4, 4j4+1)
                acc[1][f] = ffma2(mv.y, xv, acc[1][f]);  // cols (4j4+2, 4j4+3)
            }
        }
        // stash partials: jpair index jp_glob = 2*j4 + jp
        #pragma unroll
        for (int jp = 0; jp < 2; jp++)
            #pragma unroll
            for (int f = 0; f < FIN; f++)
                Ps[(q * 128 + j4 * 2 + jp) * FIN + f] = acc[jp][f];
        __syncthreads();

        // combine K-split + apply 0.1*x + 0.45*agg (+ relu on conv #3)
        if (t < 128) {
            int j0 = 2 * t, j1 = 2 * t + 1;
            #pragma unroll
            for (int f = 0; f < FIN; f++) {
                unsigned long long s = Ps[(0 * 128 + t) * FIN + f];
                s = fadd2(s, Ps[(1 * 128 + t) * FIN + f]);
                s = fadd2(s, Ps[(2 * 128 + t) * FIN + f]);
                s = fadd2(s, Ps[(3 * 128 + t) * FIN + f]);
                float2 sv = unpack2(s);
                float y0 = 0.1f * Xp[j0 * FIN + f] + 0.45f * sv.x;
                float y1 = 0.1f * Xp[j1 * FIN + f] + 0.45f * sv.y;
                if (cs == 2) { y0 = fmaxf(y0, 0.f); y1 = fmaxf(y1, 0.f); }
                Xp[j0 * FIN + f] = y0;  Xp[j1 * FIN + f] = y1;
                Xd[j0 * FIN + f] = dup2(y0);  Xd[j1 * FIN + f] = dup2(y1);
            }
        }
        __syncthreads();
    }

    // head: out_node = relu(o @ lin_w + lin_b); pool over nodes; @ fc_w + fc_b
    {
        int k = t & 127, h = t >> 7;     // two threads per hidden unit (node halves)
        float lw[FIN];
        #pragma unroll
        for (int f = 0; f < FIN; f++) lw[f] = lin_w[f * 128 + k];
        float lb = lin_b[k];
        float s = 0.f;
        int n0 = h * 128;
        for (int n = n0; n < n0 + 128; n++) {
            float v = lb;
            #pragma unroll
            for (int f = 0; f < FIN; f++) v = fmaf(Xp[n * FIN + f], lw[f], v);
            s += fmaxf(v, 0.f);
        }
        PoolBuf[h * 128 + k] = s;
    }
    __syncthreads();
    if (t < 3) {
        float s = fc_b[t];
        for (int k = 0; k < 128; k++)
            s = fmaf(PoolBuf[k] + PoolBuf[128 + k], fc_w[k * 3 + t], s);
        out[b * 3 + t] = s;
    }
}

// ---------------- launch ----------------
extern "C" void kernel_launch(void* const* d_in, const int* in_sizes, int n_in,
                              void* d_out, int out_size) {
    const float* x     = (const float*)d_in[0];
    const float* ewp   = (const float*)d_in[1];
    const float* a_uc  = (const float*)d_in[2];
    const float* b_uc  = (const float*)d_in[3];
    const float* u_pi  = (const float*)d_in[4];
    const float* u_rb  = (const float*)d_in[5];
    const float* lin_w = (const float*)d_in[6];
    const float* lin_b = (const float*)d_in[7];
    const float* fc_w  = (const float*)d_in[8];
    const float* fc_b  = (const float*)d_in[9];
    // d_in[10] = edge_index, d_in[11] = batch: structure is analytic, unused.
    float* out = (float*)d_out;

    scalar_kernel<<<1, 32>>>(a_uc, b_uc, u_pi, out);
    deg_kernel<<<N_, N_>>>(ewp);
    mats_kernel<<<N_, N_>>>(ewp, u_rb);
    conv_head_kernel<<<B_, 256>>>(x, lin_w, lin_b, fc_w, fc_b, out);
}

// round 2
// speedup vs baseline: 1.1871x; 1.1871x over previous
#include <cuda_runtime.h>
#include <math.h>

#define N_    256
#define B_    64
#define FIN   5
#define NE_   65536

// ---------------- scratch (no allocations allowed) ----------------
__device__ __align__(16) float g_mats[4 * NE_];   // [A, M0, M1, M2], row-major [i*N+j]
__device__ float g_dis[N_];
__device__ float g_logits[3];

// ---------------- packed f32x2 helpers ----------------
static __device__ __forceinline__ unsigned long long ffma2(unsigned long long a,
                                                           unsigned long long b,
                                                           unsigned long long c) {
    unsigned long long d;
    asm("fma.rn.f32x2 %0, %1, %2, %3;" : "=l"(d) : "l"(a), "l"(b), "l"(c));
    return d;
}
static __device__ __forceinline__ unsigned long long fadd2(unsigned long long a,
                                                           unsigned long long b) {
    unsigned long long d;
    asm("add.rn.f32x2 %0, %1, %2;" : "=l"(d) : "l"(a), "l"(b));
    return d;
}
static __device__ __forceinline__ unsigned long long dup2(float v) {
    unsigned long long d;
    unsigned int u = __float_as_uint(v);
    asm("mov.b64 %0, {%1, %1};" : "=l"(d) : "r"(u));
    return d;
}
static __device__ __forceinline__ float2 unpack2(unsigned long long v) {
    unsigned int lo, hi;
    asm("mov.b64 {%0, %1}, %2;" : "=r"(lo), "=r"(hi) : "l"(v));
    return make_float2(__uint_as_float(lo), __uint_as_float(hi));
}

// ---------------- digamma (double) ----------------
static __device__ double digamma_d(double x) {
    double r = 0.0;
    while (x < 8.0) { r -= 1.0 / x; x += 1.0; }
    double f = 1.0 / (x * x);
    double s = f * (1.0 / 12.0 - f * (1.0 / 120.0 - f * (1.0 / 252.0 - f * (1.0 / 240.0 - f * (1.0 / 132.0)))));
    return r + log(x) - 0.5 / x - s;
}

// ---------------- kernel 1: per-layer scalars, kld, drop_rates ----------------
__global__ void scalar_kernel(const float* __restrict__ a_uc,
                              const float* __restrict__ b_uc,
                              const float* __restrict__ u_pi,
                              float* __restrict__ out) {
    int l = threadIdx.x;
    __shared__ float kld_s[3];
    if (l < 3) {
        double au = (double)a_uc[l]; if (au < -10.0) au = -10.0;
        double bu = (double)b_uc[l]; if (bu < -10.0) bu = -10.0; if (bu > 50.0) bu = 50.0;
        double a = log1p(exp(au));
        double b = log1p(exp(bu));
        double up = (double)u_pi[l];
        if (up < 1e-6) up = 1e-6;
        if (up > 1.0 - 1e-6) up = 1.0 - 1e-6;
        double pi = pow(1.0 - pow(up, 1.0 / b), 1.0 / a);
        double logits = log(pi) - log1p(-pi);
        g_logits[l] = (float)logits;
        out[193 + l] = (float)pi;   // drop_rates
        const double euler = 0.577215664901532;
        double kld = (1.0 - 0.8 / a) * (-euler - digamma_d(b) - 1.0 / b)
                   + log(a * b + 1e-10) - log(0.8) - (b - 1.0) / b;
        kld_s[l] = (float)kld;
    }
    __syncthreads();
    if (l == 0) out[192] = kld_s[0] + kld_s[1] + kld_s[2];   // kld_loss
}

// ---------------- kernel 2: degree / dis ----------------
__global__ void deg_kernel(const float* __restrict__ ewp) {
    int i = blockIdx.x, j = threadIdx.x;
    int r = max(i, j), c = min(i, j);
    float w = ewp[(r * (r + 1)) / 2 + c];
    float v = fabsf(w);
    __shared__ float sh[8];
    #pragma unroll
    for (int o = 16; o > 0; o >>= 1) v += __shfl_xor_sync(0xffffffffu, v, o);
    if ((j & 31) == 0) sh[j >> 5] = v;
    __syncthreads();
    if (j == 0) {
        float s = 0.f;
        #pragma unroll
        for (int k = 0; k < 8; k++) s += sh[k];
        g_dis[i] = (s > 0.f) ? rsqrtf(s) : 0.f;
    }
}

// ---------------- kernel 3: build A and the three masked matrices ----------------
__global__ void mats_kernel(const float* __restrict__ ewp,
                            const float* __restrict__ u_rb) {
    int i = blockIdx.x, j = threadIdx.x;
    int r = max(i, j), c = min(i, j);
    float w = ewp[(r * (r + 1)) / 2 + c];
    float aij = g_dis[i] * w * g_dis[j];
    int e = i * N_ + j;
    g_mats[e] = aij;
    #pragma unroll
    for (int l = 0; l < 3; l++) {
        float ur = u_rb[l * NE_ + e];
        ur = fminf(fmaxf(ur, 1e-6f), 1.0f - 1e-6f);
        float t = (g_logits[l] + logf(ur) - logf(1.0f - ur)) * (1.0f / 0.6f);
        float z = 1.0f / (1.0f + expf(-t));
        g_mats[(l + 1) * NE_ + e] = z * aij;
    }
}

// ---------------- kernel 4: fused 5-conv chain + lin/relu/pool/fc head ----------
// One block per graph, 512 threads (16 warps).
// Thread t: column pair j2 = t&127 (cols 2*j2, 2*j2+1), K-quarter q = t>>7
// (rows q*64 .. q*64+63). Inner loop batches 16 independent LDG.64s into
// registers (MLP=16) before the FMA block — one L2 round-trip per 16 rows.
__global__ void __launch_bounds__(512) conv_head_kernel(
        const float* __restrict__ x,
        const float* __restrict__ lin_w, const float* __restrict__ lin_b,
        const float* __restrict__ fc_w,  const float* __restrict__ fc_b,
        float* __restrict__ out) {
    __shared__ unsigned long long Xd[N_ * FIN];        // duplicated (v,v)   10 KB
    __shared__ float Xp[N_ * FIN];                     // plain              5 KB
    __shared__ unsigned long long Ps[4 * 128 * FIN];   // K-split partials  20 KB
    __shared__ float PoolBuf[4 * 128];                 //                    2 KB

    int b = blockIdx.x, t = threadIdx.x;
    int j2 = t & 127;          // column pair
    int q  = t >> 7;           // K-quarter (64 rows)

    // load this graph's X (1280 floats over 512 threads)
    {
        const float* xb = x + b * N_ * FIN;
        for (int idx = t; idx < N_ * FIN; idx += 512) {
            float v = xb[idx];
            Xp[idx] = v;
            Xd[idx] = dup2(v);
        }
    }
    __syncthreads();

    #pragma unroll 1
    for (int cs = 0; cs < 5; cs++) {
        // matrix order: M0, A, M1, A, M2  ->  index 1,0,2,0,3
        int mi = (cs & 1) ? 0 : ((cs >> 1) + 1);
        const unsigned long long* Mv = (const unsigned long long*)(g_mats + mi * NE_);

        unsigned long long acc[FIN];
        #pragma unroll
        for (int f = 0; f < FIN; f++) acc[f] = 0ull;

        int i0 = q * 64;
        #pragma unroll 1
        for (int ii = 0; ii < 64; ii += 16) {
            unsigned long long mv[16];
            #pragma unroll
            for (int u = 0; u < 16; u++)
                mv[u] = Mv[(i0 + ii + u) * 128 + j2];     // M[i][2j2 .. 2j2+1]
            #pragma unroll
            for (int u = 0; u < 16; u++) {
                const unsigned long long* xr = &Xd[(i0 + ii + u) * FIN];
                #pragma unroll
                for (int f = 0; f < FIN; f++)
                    acc[f] = ffma2(mv[u], xr[f], acc[f]);
            }
        }
        #pragma unroll
        for (int f = 0; f < FIN; f++)
            Ps[(q * 128 + j2) * FIN + f] = acc[f];
        __syncthreads();

        // combine K-splits + apply 0.1*x + 0.45*agg (+ relu on conv #3)
        if (t < 128) {
            int j0 = 2 * t, j1 = 2 * t + 1;
            #pragma unroll
            for (int f = 0; f < FIN; f++) {
                unsigned long long s = fadd2(
                    fadd2(Ps[(0 * 128 + t) * FIN + f], Ps[(1 * 128 + t) * FIN + f]),
                    fadd2(Ps[(2 * 128 + t) * FIN + f], Ps[(3 * 128 + t) * FIN + f]));
                float2 sv = unpack2(s);
                float y0 = 0.1f * Xp[j0 * FIN + f] + 0.45f * sv.x;
                float y1 = 0.1f * Xp[j1 * FIN + f] + 0.45f * sv.y;
                if (cs == 2) { y0 = fmaxf(y0, 0.f); y1 = fmaxf(y1, 0.f); }
                Xp[j0 * FIN + f] = y0;  Xp[j1 * FIN + f] = y1;
                Xd[j0 * FIN + f] = dup2(y0);  Xd[j1 * FIN + f] = dup2(y1);
            }
        }
        __syncthreads();
    }

    // head: out_node = relu(o @ lin_w + lin_b); pool over nodes; @ fc_w + fc_b
    {
        int k = t & 127, h = t >> 7;     // 4 threads per hidden unit (node quarters)
        float lw[FIN];
        #pragma unroll
        for (int f = 0; f < FIN; f++) lw[f] = lin_w[f * 128 + k];
        float lb = lin_b[k];
        float s = 0.f;
        int n0 = h * 64;
        for (int n = n0; n < n0 + 64; n++) {
            float v = lb;
            #pragma unroll
            for (int f = 0; f < FIN; f++) v = fmaf(Xp[n * FIN + f], lw[f], v);
            s += fmaxf(v, 0.f);
        }
        PoolBuf[h * 128 + k] = s;
    }
    __syncthreads();
    if (t < 3) {
        float s = fc_b[t];
        for (int k = 0; k < 128; k++)
            s = fmaf(PoolBuf[k] + PoolBuf[128 + k] + PoolBuf[256 + k] + PoolBuf[384 + k],
                     fc_w[k * 3 + t], s);
        out[b * 3 + t] = s;
    }
}

// ---------------- launch ----------------
extern "C" void kernel_launch(void* const* d_in, const int* in_sizes, int n_in,
                              void* d_out, int out_size) {
    const float* x     = (const float*)d_in[0];
    const float* ewp   = (const float*)d_in[1];
    const float* a_uc  = (const float*)d_in[2];
    const float* b_uc  = (const float*)d_in[3];
    const float* u_pi  = (const float*)d_in[4];
    const float* u_rb  = (const float*)d_in[5];
    const float* lin_w = (const float*)d_in[6];
    const float* lin_b = (const float*)d_in[7];
    const float* fc_w  = (const float*)d_in[8];
    const float* fc_b  = (const float*)d_in[9];
    // d_in[10] = edge_index, d_in[11] = batch: structure is analytic, unused.
    float* out = (float*)d_out;

    scalar_kernel<<<1, 32>>>(a_uc, b_uc, u_pi, out);
    deg_kernel<<<N_, N_>>>(ewp);
    mats_kernel<<<N_, N_>>>(ewp, u_rb);
    conv_head_kernel<<<B_, 512>>>(x, lin_w, lin_b, fc_w, fc_b, out);
}

// round 3
// speedup vs baseline: 1.5989x; 1.3469x over previous
#include <cuda_runtime.h>
#include <math.h>

#define N_    256
#define B_    64
#define FIN   5
#define NE_   65536

// ---------------- scratch (no allocations allowed) ----------------
__device__ __align__(16) float g_mats[4 * NE_];   // [A, M0, M1, M2], row-major [i*N+j]
__device__ float g_dis[N_];
__device__ float g_logits[3];

// ---------------- packed f32x2 helpers ----------------
static __device__ __forceinline__ unsigned long long ffma2(unsigned long long a,
                                                           unsigned long long b,
                                                           unsigned long long c) {
    unsigned long long d;
    asm("fma.rn.f32x2 %0, %1, %2, %3;" : "=l"(d) : "l"(a), "l"(b), "l"(c));
    return d;
}
static __device__ __forceinline__ unsigned long long fadd2(unsigned long long a,
                                                           unsigned long long b) {
    unsigned long long d;
    asm("add.rn.f32x2 %0, %1, %2;" : "=l"(d) : "l"(a), "l"(b));
    return d;
}
static __device__ __forceinline__ unsigned long long dup2(float v) {
    unsigned long long d;
    unsigned int u = __float_as_uint(v);
    asm("mov.b64 %0, {%1, %1};" : "=l"(d) : "r"(u));
    return d;
}
static __device__ __forceinline__ float2 unpack2(unsigned long long v) {
    unsigned int lo, hi;
    asm("mov.b64 {%0, %1}, %2;" : "=r"(lo), "=r"(hi) : "l"(v));
    return make_float2(__uint_as_float(lo), __uint_as_float(hi));
}

// ---------------- digamma (double) ----------------
static __device__ double digamma_d(double x) {
    double r = 0.0;
    while (x < 8.0) { r -= 1.0 / x; x += 1.0; }
    double f = 1.0 / (x * x);
    double s = f * (1.0 / 12.0 - f * (1.0 / 120.0 - f * (1.0 / 252.0 - f * (1.0 / 240.0 - f * (1.0 / 132.0)))));
    return r + log(x) - 0.5 / x - s;
}

// ---------------- kernel 1: degree/dis + (block 0) per-layer scalars ----------
__global__ void deg_scalar_kernel(const float* __restrict__ ewp,
                                  const float* __restrict__ a_uc,
                                  const float* __restrict__ b_uc,
                                  const float* __restrict__ u_pi,
                                  float* __restrict__ out) {
    int i = blockIdx.x, j = threadIdx.x;
    int r = max(i, j), c = min(i, j);
    float w = ewp[(r * (r + 1)) / 2 + c];
    float v = fabsf(w);
    __shared__ float sh[8];
    __shared__ float kld_s[3];
    #pragma unroll
    for (int o = 16; o > 0; o >>= 1) v += __shfl_xor_sync(0xffffffffu, v, o);
    if ((j & 31) == 0) sh[j >> 5] = v;

    if (i == 0 && j >= 32 && j < 35) {   // scalar path on a spare warp of block 0
        int l = j - 32;
        double au = (double)a_uc[l]; if (au < -10.0) au = -10.0;
        double bu = (double)b_uc[l]; if (bu < -10.0) bu = -10.0; if (bu > 50.0) bu = 50.0;
        double a = log1p(exp(au));
        double b = log1p(exp(bu));
        double up = (double)u_pi[l];
        if (up < 1e-6) up = 1e-6;
        if (up > 1.0 - 1e-6) up = 1.0 - 1e-6;
        double pi = pow(1.0 - pow(up, 1.0 / b), 1.0 / a);
        double logits = log(pi) - log1p(-pi);
        g_logits[l] = (float)logits;
        out[193 + l] = (float)pi;   // drop_rates
        const double euler = 0.577215664901532;
        double kld = (1.0 - 0.8 / a) * (-euler - digamma_d(b) - 1.0 / b)
                   + log(a * b + 1e-10) - log(0.8) - (b - 1.0) / b;
        kld_s[l] = (float)kld;
    }
    __syncthreads();
    if (j == 0) {
        float s = 0.f;
        #pragma unroll
        for (int k = 0; k < 8; k++) s += sh[k];
        g_dis[i] = (s > 0.f) ? rsqrtf(s) : 0.f;
        if (i == 0) out[192] = kld_s[0] + kld_s[1] + kld_s[2];   // kld_loss
    }
}

// ---------------- kernel 2: build A and the three masked matrices ----------------
__global__ void mats_kernel(const float* __restrict__ ewp,
                            const float* __restrict__ u_rb) {
    int i = blockIdx.x, j = threadIdx.x;
    int r = max(i, j), c = min(i, j);
    float w = ewp[(r * (r + 1)) / 2 + c];
    float aij = g_dis[i] * w * g_dis[j];
    int e = i * N_ + j;
    g_mats[e] = aij;
    #pragma unroll
    for (int l = 0; l < 3; l++) {
        float ur = u_rb[l * NE_ + e];
        ur = fminf(fmaxf(ur, 1e-6f), 1.0f - 1e-6f);
        float t = (g_logits[l] + logf(ur) - logf(1.0f - ur)) * (1.0f / 0.6f);
        float z = 1.0f / (1.0f + expf(-t));
        g_mats[(l + 1) * NE_ + e] = z * aij;
    }
}

// ---------------- kernel 3: fused conv chain + head, clustered -----------------
// 128 blocks = (graph b = blockIdx.x>>1, column half c = blockIdx.x&1),
// cluster (2,1,1). 512 threads. Per conv: the 256x128 matrix slab streams into
// smem via cp.async in two 64KB halves (double buffered); compute is LDS.128 +
// packed f32x2 FMA. Each block updates its 128 columns of X locally AND in the
// peer CTA's smem (DSMEM), cluster.sync per conv.
//
// smem layout (dynamic):
#define SM_MTILE   0          // 2 * 128*128 f32 = 131072
#define SM_XD      131072     // 256*6 u64       = 12288
#define SM_XP      143360     // 256*5 f32       = 5120
#define SM_PS      148480     // 512*11 u64      = 45056
#define SM_POOL    193536     // 512 f32         = 2048
#define SM_POOLP   195584     // 128 f32         = 512
#define SM_TOTAL   196096

__global__ void __launch_bounds__(512, 1) __cluster_dims__(2, 1, 1)
conv_head_kernel(const float* __restrict__ x,
                 const float* __restrict__ lin_w, const float* __restrict__ lin_b,
                 const float* __restrict__ fc_w,  const float* __restrict__ fc_b,
                 float* __restrict__ out) {
    extern __shared__ __align__(16) char sm_[];
    float*              Mtile = (float*)(sm_ + SM_MTILE);
    unsigned long long* Xd    = (unsigned long long*)(sm_ + SM_XD);
    float*              Xp    = (float*)(sm_ + SM_XP);
    unsigned long long* Ps    = (unsigned long long*)(sm_ + SM_PS);
    float*              Pool  = (float*)(sm_ + SM_POOL);
    float*              PoolP = (float*)(sm_ + SM_POOLP);

    const int t  = threadIdx.x;
    const int j4 = t & 31;              // 4-col group within the 128-col slab
    const int q  = t >> 5;              // 0..15 K-split (8 rows per half)
    const int b  = blockIdx.x >> 1;
    const int c  = blockIdx.x & 1;      // == cluster rank
    const unsigned prank = (unsigned)(c ^ 1);

    // async-copy one 128-row x 128-col half-slab into smem
    auto issue_half = [&](const float* gsrc, float* stile) {
        #pragma unroll
        for (int k = 0; k < 8; k++) {
            int o = (k << 9) + t;
            int row = o >> 5, seg = (o & 31) << 2;
            const float* src = gsrc + row * 256 + seg;
            unsigned int dst = (unsigned int)__cvta_generic_to_shared(&stile[row * 128 + seg]);
            asm volatile("cp.async.cg.shared.global [%0], [%1], 16;" :: "r"(dst), "l"(src));
        }
        asm volatile("cp.async.commit_group;" ::: "memory");
    };

    // prefetch conv 0 (matrix M0 = index 1)
    {
        const float* g0 = g_mats + 1 * NE_ + c * 128;
        issue_half(g0, Mtile);
        issue_half(g0 + 128 * 256, Mtile + 16384);
    }

    // load this graph's X
    {
        const float* xb = x + b * (N_ * FIN);
        for (int idx = t; idx < N_ * FIN; idx += 512) {
            float v = xb[idx];
            int i = idx / 5, f = idx - i * 5;
            Xp[idx] = v;
            Xd[i * 6 + f] = dup2(v);
        }
    }

    // peer smem windows for the X exchange
    unsigned int peerXp, peerXd;
    {
        unsigned int lxp = (unsigned int)__cvta_generic_to_shared(Xp);
        unsigned int lxd = (unsigned int)__cvta_generic_to_shared(Xd);
        asm("mapa.shared::cluster.u32 %0, %1, %2;" : "=r"(peerXp) : "r"(lxp), "r"(prank));
        asm("mapa.shared::cluster.u32 %0, %1, %2;" : "=r"(peerXd) : "r"(lxd), "r"(prank));
    }

    unsigned long long accA[FIN], accB[FIN];
    const int qq8 = q * 8;

    #pragma unroll 1
    for (int cs = 0; cs < 5; cs++) {
        #pragma unroll
        for (int f = 0; f < FIN; f++) { accA[f] = 0ull; accB[f] = 0ull; }

        // half 0 ready?
        asm volatile("cp.async.wait_group 1;" ::: "memory");
        __syncthreads();

        #pragma unroll
        for (int r_ = 0; r_ < 8; r_++) {
            int row = qq8 + r_;
            ulonglong2 mv = *(const ulonglong2*)&Mtile[row * 128 + j4 * 4];
            const unsigned long long* xr = &Xd[row * 6];
            ulonglong2 x01 = *(const ulonglong2*)xr;
            ulonglong2 x23 = *(const ulonglong2*)(xr + 2);
            unsigned long long x4 = xr[4];
            accA[0] = ffma2(mv.x, x01.x, accA[0]);  accB[0] = ffma2(mv.y, x01.x, accB[0]);
            accA[1] = ffma2(mv.x, x01.y, accA[1]);  accB[1] = ffma2(mv.y, x01.y, accB[1]);
            accA[2] = ffma2(mv.x, x23.x, accA[2]);  accB[2] = ffma2(mv.y, x23.x, accB[2]);
            accA[3] = ffma2(mv.x, x23.y, accA[3]);  accB[3] = ffma2(mv.y, x23.y, accB[3]);
            accA[4] = ffma2(mv.x, x4,    accA[4]);  accB[4] = ffma2(mv.y, x4,    accB[4]);
        }

        // half 1 ready?
        asm volatile("cp.async.wait_group 0;" ::: "memory");
        __syncthreads();

        #pragma unroll
        for (int r_ = 0; r_ < 8; r_++) {
            int row = qq8 + r_;
            ulonglong2 mv = *(const ulonglong2*)&Mtile[16384 + row * 128 + j4 * 4];
            const unsigned long long* xr = &Xd[(128 + row) * 6];
            ulonglong2 x01 = *(const ulonglong2*)xr;
            ulonglong2 x23 = *(const ulonglong2*)(xr + 2);
            unsigned long long x4 = xr[4];
            accA[0] = ffma2(mv.x, x01.x, accA[0]);  accB[0] = ffma2(mv.y, x01.x, accB[0]);
            accA[1] = ffma2(mv.x, x01.y, accA[1]);  accB[1] = ffma2(mv.y, x01.y, accB[1]);
            accA[2] = ffma2(mv.x, x23.x, accA[2]);  accB[2] = ffma2(mv.y, x23.x, accB[2]);
            accA[3] = ffma2(mv.x, x23.y, accA[3]);  accB[3] = ffma2(mv.y, x23.y, accB[3]);
            accA[4] = ffma2(mv.x, x4,    accA[4]);  accB[4] = ffma2(mv.y, x4,    accB[4]);
        }

        // stash K-split partials
        {
            int base = (q * 32 + j4) * 11;
            #pragma unroll
            for (int f = 0; f < FIN; f++) { Ps[base + f] = accA[f]; Ps[base + 5 + f] = accB[f]; }
        }
        __syncthreads();   // everyone done reading Mtile & writing Ps

        // prefetch next conv's matrix (M order: M0, A, M1, A, M2 -> 1,0,2,0,3)
        if (cs < 4) {
            int mi = ((cs + 1) & 1) ? 0 : (((cs + 1) >> 1) + 1);
            const float* gsrc = g_mats + mi * NE_ + c * 128;
            issue_half(gsrc, Mtile);
            issue_half(gsrc + 128 * 256, Mtile + 16384);
        }

        // combine 16 K-splits + 0.1*x + 0.45*agg (+relu on conv #3); update X local+peer
        if (t < 320) {
            int f = t % 5, pc = t / 5;
            int j4c = pc >> 1, a = pc & 1;
            unsigned long long s = Ps[j4c * 11 + a * 5 + f];
            #pragma unroll
            for (int qq = 1; qq < 16; qq++)
                s = fadd2(s, Ps[(qq * 32 + j4c) * 11 + a * 5 + f]);
            float2 sv = unpack2(s);
            int g0c = c * 128 + 4 * j4c + 2 * a;
            float y0 = 0.1f * Xp[g0c * 5 + f]       + 0.45f * sv.x;
            float y1 = 0.1f * Xp[(g0c + 1) * 5 + f] + 0.45f * sv.y;
            if (cs == 2) { y0 = fmaxf(y0, 0.f); y1 = fmaxf(y1, 0.f); }
            Xp[g0c * 5 + f] = y0;  Xp[(g0c + 1) * 5 + f] = y1;
            unsigned long long d0 = dup2(y0), d1 = dup2(y1);
            Xd[g0c * 6 + f] = d0;  Xd[(g0c + 1) * 6 + f] = d1;
            if (cs < 4) {   // peer update (head only needs local half after last conv)
                asm volatile("st.shared::cluster.f32 [%0], %1;" :: "r"(peerXp + (g0c * 5 + f) * 4), "f"(y0));
                asm volatile("st.shared::cluster.f32 [%0], %1;" :: "r"(peerXp + ((g0c + 1) * 5 + f) * 4), "f"(y1));
                asm volatile("st.shared::cluster.b64 [%0], %1;" :: "r"(peerXd + (g0c * 6 + f) * 8), "l"(d0));
                asm volatile("st.shared::cluster.b64 [%0], %1;" :: "r"(peerXd + ((g0c + 1) * 6 + f) * 8), "l"(d1));
            }
        }
        asm volatile("barrier.cluster.arrive.aligned;" ::: "memory");
        asm volatile("barrier.cluster.wait.aligned;" ::: "memory");
    }

    // ---- head: relu(o @ lin_w + lin_b), pool over this block's 128 nodes ----
    {
        int k = t & 127, h2 = t >> 7;
        float lw0 = lin_w[k], lw1 = lin_w[128 + k], lw2 = lin_w[256 + k],
              lw3 = lin_w[384 + k], lw4 = lin_w[512 + k];
        float lb = lin_b[k];
        float s = 0.f;
        int n0 = c * 128 + h2 * 32;
        for (int n = n0; n < n0 + 32; n++) {
            const float* xr = &Xp[n * 5];
            float v = lb;
            v = fmaf(xr[0], lw0, v);
            v = fmaf(xr[1], lw1, v);
            v = fmaf(xr[2], lw2, v);
            v = fmaf(xr[3], lw3, v);
            v = fmaf(xr[4], lw4, v);
            s += fmaxf(v, 0.f);
        }
        Pool[h2 * 128 + k] = s;
    }
    __syncthreads();
    if (t < 128) {
        float p = Pool[t] + Pool[128 + t] + Pool[256 + t] + Pool[384 + t];
        if (c) {
            unsigned int lpp = (unsigned int)__cvta_generic_to_shared(&PoolP[t]);
            unsigned int rpp;
            asm("mapa.shared::cluster.u32 %0, %1, %2;" : "=r"(rpp) : "r"(lpp), "r"(prank));
            asm volatile("st.shared::cluster.f32 [%0], %1;" :: "r"(rpp), "f"(p));
        } else {
            Pool[t] = p;
        }
    }
    asm volatile("barrier.cluster.arrive.aligned;" ::: "memory");
    asm volatile("barrier.cluster.wait.aligned;" ::: "memory");
    if (c == 0 && t < 3) {
        float s = fc_b[t];
        for (int k2 = 0; k2 < 128; k2++)
            s = fmaf(Pool[k2] + PoolP[k2], fc_w[k2 * 3 + t], s);
        out[b * 3 + t] = s;
    }
}

// ---------------- launch ----------------
extern "C" void kernel_launch(void* const* d_in, const int* in_sizes, int n_in,
                              void* d_out, int out_size) {
    const float* x     = (const float*)d_in[0];
    const float* ewp   = (const float*)d_in[1];
    const float* a_uc  = (const float*)d_in[2];
    const float* b_uc  = (const float*)d_in[3];
    const float* u_pi  = (const float*)d_in[4];
    const float* u_rb  = (const float*)d_in[5];
    const float* lin_w = (const float*)d_in[6];
    const float* lin_b = (const float*)d_in[7];
    const float* fc_w  = (const float*)d_in[8];
    const float* fc_b  = (const float*)d_in[9];
    // d_in[10] = edge_index, d_in[11] = batch: structure is analytic, unused.
    float* out = (float*)d_out;

    cudaFuncSetAttribute(conv_head_kernel,
                         cudaFuncAttributeMaxDynamicSharedMemorySize, SM_TOTAL);

    deg_scalar_kernel<<<N_, N_>>>(ewp, a_uc, b_uc, u_pi, out);
    mats_kernel<<<N_, N_>>>(ewp, u_rb);
    conv_head_kernel<<<2 * B_, 512, SM_TOTAL>>>(x, lin_w, lin_b, fc_w, fc_b, out);
}

// round 4
// speedup vs baseline: 2.4508x; 1.5328x over previous
#include <cuda_runtime.h>
#include <math.h>

#define N_    256
#define B_    64
#define FIN   5
#define NE_   65536

// ---------------- scratch (no allocations allowed) ----------------
__device__ __align__(16) float g_mats[4 * NE_];   // [A, M0, M1, M2], row-major [i*N+j]
__device__ float g_dis[N_];
__device__ float g_logits[3];

// ---------------- packed f32x2 helpers ----------------
static __device__ __forceinline__ unsigned long long ffma2(unsigned long long a,
                                                           unsigned long long b,
                                                           unsigned long long c) {
    unsigned long long d;
    asm("fma.rn.f32x2 %0, %1, %2, %3;" : "=l"(d) : "l"(a), "l"(b), "l"(c));
    return d;
}
static __device__ __forceinline__ unsigned long long fadd2(unsigned long long a,
                                                           unsigned long long b) {
    unsigned long long d;
    asm("add.rn.f32x2 %0, %1, %2;" : "=l"(d) : "l"(a), "l"(b));
    return d;
}
static __device__ __forceinline__ unsigned long long dup2(float v) {
    unsigned long long d;
    unsigned int u = __float_as_uint(v);
    asm("mov.b64 %0, {%1, %1};" : "=l"(d) : "r"(u));
    return d;
}
static __device__ __forceinline__ float2 unpack2(unsigned long long v) {
    unsigned int lo, hi;
    asm("mov.b64 {%0, %1}, %2;" : "=r"(lo), "=r"(hi) : "l"(v));
    return make_float2(__uint_as_float(lo), __uint_as_float(hi));
}

// ---------------- digamma (fp32) ----------------
static __device__ float digamma_f(float x) {
    float r = 0.0f;
    #pragma unroll 8
    while (x < 8.0f) { r -= 1.0f / x; x += 1.0f; }
    float f = 1.0f / (x * x);
    float s = f * (1.0f / 12.0f - f * (1.0f / 120.0f - f * (1.0f / 252.0f
            - f * (1.0f / 240.0f - f * (1.0f / 132.0f)))));
    return r + logf(x) - 0.5f / x - s;
}

// ---------------- kernel 1: degree/dis + (block 0) fp32 scalar path ----------
__global__ void deg_scalar_kernel(const float* __restrict__ ewp,
                                  const float* __restrict__ a_uc,
                                  const float* __restrict__ b_uc,
                                  const float* __restrict__ u_pi,
                                  float* __restrict__ out) {
    int i = blockIdx.x, j = threadIdx.x;
    int r = max(i, j), c = min(i, j);
    float w = ewp[(r * (r + 1)) / 2 + c];
    float v = fabsf(w);
    __shared__ float sh[8];
    __shared__ float kld_s[3];
    #pragma unroll
    for (int o = 16; o > 0; o >>= 1) v += __shfl_xor_sync(0xffffffffu, v, o);
    if ((j & 31) == 0) sh[j >> 5] = v;

    if (i == 0 && j >= 32 && j < 35) {   // scalar path on a spare warp of block 0 (fp32)
        int l = j - 32;
        float au = a_uc[l]; if (au < -10.0f) au = -10.0f;
        float bu = b_uc[l]; if (bu < -10.0f) bu = -10.0f; if (bu > 50.0f) bu = 50.0f;
        float a = log1pf(expf(au));
        float b = log1pf(expf(bu));
        float up = u_pi[l];
        up = fminf(fmaxf(up, 1e-6f), 1.0f - 1e-6f);
        float pi = powf(1.0f - powf(up, 1.0f / b), 1.0f / a);
        float logits = logf(pi) - log1pf(-pi);
        g_logits[l] = logits;
        out[193 + l] = pi;   // drop_rates
        const float euler = 0.577215664901532f;
        float kld = (1.0f - 0.8f / a) * (-euler - digamma_f(b) - 1.0f / b)
                  + logf(a * b + 1e-10f) - logf(0.8f) - (b - 1.0f) / b;
        kld_s[l] = kld;
    }
    __syncthreads();
    if (j == 0) {
        float s = 0.f;
        #pragma unroll
        for (int k = 0; k < 8; k++) s += sh[k];
        g_dis[i] = (s > 0.f) ? rsqrtf(s) : 0.f;
        if (i == 0) out[192] = kld_s[0] + kld_s[1] + kld_s[2];   // kld_loss
    }
}

// ---------------- kernel 2: build A and the three masked matrices ----------------
__global__ void mats_kernel(const float* __restrict__ ewp,
                            const float* __restrict__ u_rb) {
    int i = blockIdx.x, j = threadIdx.x;
    int r = max(i, j), c = min(i, j);
    float w = ewp[(r * (r + 1)) / 2 + c];
    float aij = g_dis[i] * w * g_dis[j];
    int e = i * N_ + j;
    g_mats[e] = aij;
    #pragma unroll
    for (int l = 0; l < 3; l++) {
        float ur = u_rb[l * NE_ + e];
        ur = fminf(fmaxf(ur, 1e-6f), 1.0f - 1e-6f);
        float t = (g_logits[l] + logf(ur) - logf(1.0f - ur)) * (1.0f / 0.6f);
        float z = 1.0f / (1.0f + expf(-t));
        g_mats[(l + 1) * NE_ + e] = z * aij;
    }
}

// ---------------- kernel 3: fused conv chain + head, clustered -----------------
// 128 blocks = (graph b = blockIdx.x>>1, column half c = blockIdx.x&1),
// cluster (2,1,1). 512 threads. Per conv: the 256x128 matrix slab streams into
// smem via cp.async in two 64KB halves (double buffered); compute is LDS.128 +
// packed f32x2 FMA. Each block updates its 128 columns of X locally AND in the
// peer CTA's smem (DSMEM), cluster.sync per conv.
//
// smem layout (dynamic):
#define SM_MTILE   0          // 2 * 128*128 f32 = 131072
#define SM_XD      131072     // 256*6 u64       = 12288
#define SM_XP      143360     // 256*5 f32       = 5120
#define SM_PS      148480     // 512*11 u64      = 45056
#define SM_POOL    193536     // 512 f32         = 2048
#define SM_POOLP   195584     // 128 f32         = 512
#define SM_TOTAL   196096

__global__ void __launch_bounds__(512, 1) __cluster_dims__(2, 1, 1)
conv_head_kernel(const float* __restrict__ x,
                 const float* __restrict__ lin_w, const float* __restrict__ lin_b,
                 const float* __restrict__ fc_w,  const float* __restrict__ fc_b,
                 float* __restrict__ out) {
    extern __shared__ __align__(16) char sm_[];
    float*              Mtile = (float*)(sm_ + SM_MTILE);
    unsigned long long* Xd    = (unsigned long long*)(sm_ + SM_XD);
    float*              Xp    = (float*)(sm_ + SM_XP);
    unsigned long long* Ps    = (unsigned long long*)(sm_ + SM_PS);
    float*              Pool  = (float*)(sm_ + SM_POOL);
    float*              PoolP = (float*)(sm_ + SM_POOLP);

    const int t  = threadIdx.x;
    const int j4 = t & 31;              // 4-col group within the 128-col slab
    const int q  = t >> 5;              // 0..15 K-split (8 rows per half)
    const int b  = blockIdx.x >> 1;
    const int c  = blockIdx.x & 1;      // == cluster rank
    const unsigned prank = (unsigned)(c ^ 1);

    // async-copy one 128-row x 128-col half-slab into smem
    auto issue_half = [&](const float* gsrc, float* stile) {
        #pragma unroll
        for (int k = 0; k < 8; k++) {
            int o = (k << 9) + t;
            int row = o >> 5, seg = (o & 31) << 2;
            const float* src = gsrc + row * 256 + seg;
            unsigned int dst = (unsigned int)__cvta_generic_to_shared(&stile[row * 128 + seg]);
            asm volatile("cp.async.cg.shared.global [%0], [%1], 16;" :: "r"(dst), "l"(src));
        }
        asm volatile("cp.async.commit_group;" ::: "memory");
    };

    // prefetch conv 0 (matrix M0 = index 1)
    {
        const float* g0 = g_mats + 1 * NE_ + c * 128;
        issue_half(g0, Mtile);
        issue_half(g0 + 128 * 256, Mtile + 16384);
    }

    // load this graph's X
    {
        const float* xb = x + b * (N_ * FIN);
        for (int idx = t; idx < N_ * FIN; idx += 512) {
            float v = xb[idx];
            int i = idx / 5, f = idx - i * 5;
            Xp[idx] = v;
            Xd[i * 6 + f] = dup2(v);
        }
    }

    // peer smem windows for the X exchange
    unsigned int peerXp, peerXd;
    {
        unsigned int lxp = (unsigned int)__cvta_generic_to_shared(Xp);
        unsigned int lxd = (unsigned int)__cvta_generic_to_shared(Xd);
        asm("mapa.shared::cluster.u32 %0, %1, %2;" : "=r"(peerXp) : "r"(lxp), "r"(prank));
        asm("mapa.shared::cluster.u32 %0, %1, %2;" : "=r"(peerXd) : "r"(lxd), "r"(prank));
    }

    unsigned long long accA[FIN], accB[FIN];
    const int qq8 = q * 8;

    #pragma unroll 1
    for (int cs = 0; cs < 5; cs++) {
        #pragma unroll
        for (int f = 0; f < FIN; f++) { accA[f] = 0ull; accB[f] = 0ull; }

        // half 0 ready?
        asm volatile("cp.async.wait_group 1;" ::: "memory");
        __syncthreads();

        #pragma unroll
        for (int r_ = 0; r_ < 8; r_++) {
            int row = qq8 + r_;
            ulonglong2 mv = *(const ulonglong2*)&Mtile[row * 128 + j4 * 4];
            const unsigned long long* xr = &Xd[row * 6];
            ulonglong2 x01 = *(const ulonglong2*)xr;
            ulonglong2 x23 = *(const ulonglong2*)(xr + 2);
            unsigned long long x4 = xr[4];
            accA[0] = ffma2(mv.x, x01.x, accA[0]);  accB[0] = ffma2(mv.y, x01.x, accB[0]);
            accA[1] = ffma2(mv.x, x01.y, accA[1]);  accB[1] = ffma2(mv.y, x01.y, accB[1]);
            accA[2] = ffma2(mv.x, x23.x, accA[2]);  accB[2] = ffma2(mv.y, x23.x, accB[2]);
            accA[3] = ffma2(mv.x, x23.y, accA[3]);  accB[3] = ffma2(mv.y, x23.y, accB[3]);
            accA[4] = ffma2(mv.x, x4,    accA[4]);  accB[4] = ffma2(mv.y, x4,    accB[4]);
        }

        // half 1 ready?
        asm volatile("cp.async.wait_group 0;" ::: "memory");
        __syncthreads();

        #pragma unroll
        for (int r_ = 0; r_ < 8; r_++) {
            int row = qq8 + r_;
            ulonglong2 mv = *(const ulonglong2*)&Mtile[16384 + row * 128 + j4 * 4];
            const unsigned long long* xr = &Xd[(128 + row) * 6];
            ulonglong2 x01 = *(const ulonglong2*)xr;
            ulonglong2 x23 = *(const ulonglong2*)(xr + 2);
            unsigned long long x4 = xr[4];
            accA[0] = ffma2(mv.x, x01.x, accA[0]);  accB[0] = ffma2(mv.y, x01.x, accB[0]);
            accA[1] = ffma2(mv.x, x01.y, accA[1]);  accB[1] = ffma2(mv.y, x01.y, accB[1]);
            accA[2] = ffma2(mv.x, x23.x, accA[2]);  accB[2] = ffma2(mv.y, x23.x, accB[2]);
            accA[3] = ffma2(mv.x, x23.y, accA[3]);  accB[3] = ffma2(mv.y, x23.y, accB[3]);
            accA[4] = ffma2(mv.x, x4,    accA[4]);  accB[4] = ffma2(mv.y, x4,    accB[4]);
        }

        // stash K-split partials
        {
            int base = (q * 32 + j4) * 11;
            #pragma unroll
            for (int f = 0; f < FIN; f++) { Ps[base + f] = accA[f]; Ps[base + 5 + f] = accB[f]; }
        }
        __syncthreads();   // everyone done reading Mtile & writing Ps

        // prefetch next conv's matrix (M order: M0, A, M1, A, M2 -> 1,0,2,0,3)
        if (cs < 4) {
            int mi = ((cs + 1) & 1) ? 0 : (((cs + 1) >> 1) + 1);
            const float* gsrc = g_mats + mi * NE_ + c * 128;
            issue_half(gsrc, Mtile);
            issue_half(gsrc + 128 * 256, Mtile + 16384);
        }

        // combine 16 K-splits + 0.1*x + 0.45*agg (+relu on conv #3); update X local+peer
        if (t < 320) {
            int f = t % 5, pc = t / 5;
            int j4c = pc >> 1, a = pc & 1;
            unsigned long long s = Ps[j4c * 11 + a * 5 + f];
            #pragma unroll
            for (int qq = 1; qq < 16; qq++)
                s = fadd2(s, Ps[(qq * 32 + j4c) * 11 + a * 5 + f]);
            float2 sv = unpack2(s);
            int g0c = c * 128 + 4 * j4c + 2 * a;
            float y0 = 0.1f * Xp[g0c * 5 + f]       + 0.45f * sv.x;
            float y1 = 0.1f * Xp[(g0c + 1) * 5 + f] + 0.45f * sv.y;
            if (cs == 2) { y0 = fmaxf(y0, 0.f); y1 = fmaxf(y1, 0.f); }
            Xp[g0c * 5 + f] = y0;  Xp[(g0c + 1) * 5 + f] = y1;
            unsigned long long d0 = dup2(y0), d1 = dup2(y1);
            Xd[g0c * 6 + f] = d0;  Xd[(g0c + 1) * 6 + f] = d1;
            if (cs < 4) {   // peer update (head only needs local half after last conv)
                asm volatile("st.shared::cluster.f32 [%0], %1;" :: "r"(peerXp + (g0c * 5 + f) * 4), "f"(y0));
                asm volatile("st.shared::cluster.f32 [%0], %1;" :: "r"(peerXp + ((g0c + 1) * 5 + f) * 4), "f"(y1));
                asm volatile("st.shared::cluster.b64 [%0], %1;" :: "r"(peerXd + (g0c * 6 + f) * 8), "l"(d0));
                asm volatile("st.shared::cluster.b64 [%0], %1;" :: "r"(peerXd + ((g0c + 1) * 6 + f) * 8), "l"(d1));
            }
        }
        asm volatile("barrier.cluster.arrive.aligned;" ::: "memory");
        asm volatile("barrier.cluster.wait.aligned;" ::: "memory");
    }

    // ---- head: relu(o @ lin_w + lin_b), pool over this block's 128 nodes ----
    {
        int k = t & 127, h2 = t >> 7;
        float lw0 = lin_w[k], lw1 = lin_w[128 + k], lw2 = lin_w[256 + k],
              lw3 = lin_w[384 + k], lw4 = lin_w[512 + k];
        float lb = lin_b[k];
        float s = 0.f;
        int n0 = c * 128 + h2 * 32;
        for (int n = n0; n < n0 + 32; n++) {
            const float* xr = &Xp[n * 5];
            float v = lb;
            v = fmaf(xr[0], lw0, v);
            v = fmaf(xr[1], lw1, v);
            v = fmaf(xr[2], lw2, v);
            v = fmaf(xr[3], lw3, v);
            v = fmaf(xr[4], lw4, v);
            s += fmaxf(v, 0.f);
        }
        Pool[h2 * 128 + k] = s;
    }
    __syncthreads();
    if (t < 128) {
        float p = Pool[t] + Pool[128 + t] + Pool[256 + t] + Pool[384 + t];
        if (c) {
            unsigned int lpp = (unsigned int)__cvta_generic_to_shared(&PoolP[t]);
            unsigned int rpp;
            asm("mapa.shared::cluster.u32 %0, %1, %2;" : "=r"(rpp) : "r"(lpp), "r"(prank));
            asm volatile("st.shared::cluster.f32 [%0], %1;" :: "r"(rpp), "f"(p));
        } else {
            Pool[t] = p;
        }
    }
    asm volatile("barrier.cluster.arrive.aligned;" ::: "memory");
    asm volatile("barrier.cluster.wait.aligned;" ::: "memory");
    if (c == 0 && t < 3) {
        float s = fc_b[t];
        for (int k2 = 0; k2 < 128; k2++)
            s = fmaf(Pool[k2] + PoolP[k2], fc_w[k2 * 3 + t], s);
        out[b * 3 + t] = s;
    }
}

// ---------------- launch ----------------
extern "C" void kernel_launch(void* const* d_in, const int* in_sizes, int n_in,
                              void* d_out, int out_size) {
    const float* x     = (const float*)d_in[0];
    const float* ewp   = (const float*)d_in[1];
    const float* a_uc  = (const float*)d_in[2];
    const float* b_uc  = (const float*)d_in[3];
    const float* u_pi  = (const float*)d_in[4];
    const float* u_rb  = (const float*)d_in[5];
    const float* lin_w = (const float*)d_in[6];
    const float* lin_b = (const float*)d_in[7];
    const float* fc_w  = (const float*)d_in[8];
    const float* fc_b  = (const float*)d_in[9];
    // d_in[10] = edge_index, d_in[11] = batch: structure is analytic, unused.
    float* out = (float*)d_out;

    cudaFuncSetAttribute(conv_head_kernel,
                         cudaFuncAttributeMaxDynamicSharedMemorySize, SM_TOTAL);

    deg_scalar_kernel<<<N_, N_>>>(ewp, a_uc, b_uc, u_pi, out);
    mats_kernel<<<N_, N_>>>(ewp, u_rb);
    conv_head_kernel<<<2 * B_, 512, SM_TOTAL>>>(x, lin_w, lin_b, fc_w, fc_b, out);
}